// round 12
// baseline (speedup 1.0000x reference)
#include <cuda_runtime.h>

// Problem dims
#define BB 16
#define WORDS 32
#define DIM 256
#define HEADS 8
#define DH 32
#define INNER 256
#define JJ 256     // WORDS*HEADS
#define IW 32      // output capsules (WORDS)
#define EE 256     // INNER

#define U_BSTRIDE ((size_t)JJ * IW * EE)

// ---------------- scratch (device globals; no allocations) ----------------
__device__ float g_xh[BB * JJ * DH];                  // [b][j][d]
__device__ float g_u[(size_t)BB * JJ * IW * EE];      // [b][j][i][e]  (128 MiB)
__device__ float g_S[3][BB * IW * EE];                // s accumulators per iter
__device__ float g_blog[BB * JJ * IW];                // routing logits

// ---------------- f32x2 helpers ----------------
typedef unsigned long long u64;

__device__ __forceinline__ u64 pack2(float lo, float hi) {
    u64 r;
    asm("mov.b64 %0, {%1, %2};" : "=l"(r)
        : "r"(__float_as_uint(lo)), "r"(__float_as_uint(hi)));
    return r;
}
__device__ __forceinline__ void unpack2(u64 v, float& lo, float& hi) {
    unsigned a, b;
    asm("mov.b64 {%0, %1}, %2;" : "=r"(a), "=r"(b) : "l"(v));
    lo = __uint_as_float(a);
    hi = __uint_as_float(b);
}
__device__ __forceinline__ void fma2(u64& acc, u64 a, u64 b) {
    asm("fma.rn.f32x2 %0, %1, %2, %0;" : "+l"(acc) : "l"(a), "l"(b));
}
__device__ __forceinline__ void add2(u64& acc, u64 a) {
    asm("add.rn.f32x2 %0, %1, %2;" : "=l"(acc) : "l"(acc), "l"(a));
}

// ---------------- zero kernels ----------------
__global__ void k_zeroA() {   // S0 + S1
    int t = blockIdx.x * 256 + threadIdx.x;
    float4* z = (float4*)(&g_S[0][0]);
#pragma unroll
    for (int r = 0; r < 4; r++) z[t + r * 16384] = make_float4(0.f, 0.f, 0.f, 0.f);
}
__global__ void k_zeroB() {   // S2
    int t = blockIdx.x * 256 + threadIdx.x;
    float4* z = (float4*)(&g_S[2][0]);
#pragma unroll
    for (int r = 0; r < 4; r++) z[t + r * 8192] = make_float4(0.f, 0.f, 0.f, 0.f);
}

// ---------------- K1: inner projection ----------------
__global__ void __launch_bounds__(256) k_proj_in(const float* __restrict__ x,
                                                 const float* __restrict__ Wi,
                                                 const float* __restrict__ bi) {
    extern __shared__ float dynpi[];
    float* xs = dynpi;              // [32][256]  32 KB
    float* ws = dynpi + 8192;       // [32][257]

    int eb = blockIdx.x;   // 0..7
    int b  = blockIdx.y;   // 0..15
    int tid = threadIdx.x;

    {
        const float4* xg = (const float4*)(x + (size_t)b * 32 * DIM);
        float4* xs4 = (float4*)xs;
#pragma unroll
        for (int r = 0; r < 8; r++) xs4[tid + r * 256] = xg[tid + r * 256];

        int rr = tid >> 5, c = tid & 31;
        for (int row = rr; row < 32; row += 8) {
            const float* wr = Wi + (size_t)(eb * 32 + row) * DIM;
#pragma unroll
            for (int kk = 0; kk < 8; kk++)
                ws[row * 257 + kk * 32 + c] = wr[kk * 32 + c];
        }
    }
    __syncthreads();

    int el = tid & 31;
    int n0 = (tid >> 5) * 4;
    float acc[4] = {0.f, 0.f, 0.f, 0.f};

#pragma unroll 4
    for (int k = 0; k < 256; k++) {
        float wv = ws[el * 257 + k];
#pragma unroll
        for (int r = 0; r < 4; r++)
            acc[r] = fmaf(xs[(n0 + r) * 256 + k], wv, acc[r]);
    }

    int ee = eb * 32 + el;
    float bv = bi[ee];
    int h = ee >> 5, d = ee & 31;
#pragma unroll
    for (int r = 0; r < 4; r++) {
        int n = n0 + r;
        g_xh[((size_t)b * JJ + n * HEADS + h) * DH + d] = acc[r] + bv;
    }
}

// ---------------- K2: u_hat einsum, 2i x 8b threads, ring-3, 1 sync/jj -----
__global__ void __launch_bounds__(256, 2) k_uhat(const float* __restrict__ W,
                                                 const float* __restrict__ bias) {
    extern __shared__ __align__(16) float dyn[];
    float4* ring = (float4*)dyn;             // [3][2048 float4] = 96 KB
    float*  sxh  = dyn + 3 * 8192;           // [8][32][16] = 16 KB

    int jb = blockIdx.x;   // 0..31
    int ib = blockIdx.y;   // 0..15
    int eh = blockIdx.z;   // 0..1
    int tid = threadIdx.x; // 0..255
    int el  = tid & 127;
    int bh  = tid >> 7;    // 0..1
    int b0  = bh * 8;
    int e   = eh * 128 + el;
    int i0  = ib * 2;

    for (int idx = tid; idx < 4096; idx += 256) {
        int jj  = idx >> 9;
        int rem = idx & 511;
        int b   = rem >> 5;
        int d   = rem & 31;
        sxh[jj * 512 + d * 16 + b] =
            g_xh[((size_t)b * JJ + jb * 8 + jj) * DH + d];
    }

    float bv[2][8];
#pragma unroll
    for (int i2 = 0; i2 < 2; i2++)
#pragma unroll
        for (int jj = 0; jj < 8; jj++)
            bv[i2][jj] = bias[((size_t)(jb * 8 + jj) * IW + i0 + i2) * EE + e];

    auto issue = [&](int jj) {
        float4* dst = ring + (jj % 3) * 2048;
        const float4* s0 = (const float4*)W +
            (((size_t)(jb * 8 + jj) * IW + i0) * EE + (size_t)eh * 128) * 8;
        const float4* s1 = (const float4*)W +
            (((size_t)(jb * 8 + jj) * IW + i0 + 1) * EE + (size_t)eh * 128) * 8;
#pragma unroll
        for (int k = 0; k < 8; k++) {
            int idx = tid + k * 256;           // 0..2047
            int ih  = idx >> 10;               // 0..1
            int wi  = idx & 1023;
            int er  = wi >> 3, q = wi & 7;
            unsigned sp = (unsigned)__cvta_generic_to_shared(
                &dst[ih * 1024 + ((er << 3) | (q ^ (er & 7)))]);
            const float4* src = (ih == 0) ? (s0 + wi) : (s1 + wi);
            asm volatile("cp.async.cg.shared.global [%0], [%1], 16;"
                         :: "r"(sp), "l"(src));
        }
        asm volatile("cp.async.commit_group;");
    };

    issue(0);
    issue(1);
    issue(2);

    u64 sacc[2][4];
#pragma unroll
    for (int i2 = 0; i2 < 2; i2++)
#pragma unroll
        for (int p = 0; p < 4; p++) sacc[i2][p] = 0ull;

    asm volatile("cp.async.wait_group 2;");
    __syncthreads();   // stage 0 visible; sxh ready

    for (int jj = 0; jj < 8; jj++) {
        const float4* sw = ring + (jj % 3) * 2048;
        const float*  sx = sxh + jj * 512;

        u64 acc[2][4];
#pragma unroll
        for (int i2 = 0; i2 < 2; i2++)
#pragma unroll
            for (int p = 0; p < 4; p++) acc[i2][p] = 0ull;

#pragma unroll
        for (int q = 0; q < 8; q++) {
            float4 w0 = sw[(el << 3) | (q ^ (el & 7))];
            float4 w1 = sw[1024 + ((el << 3) | (q ^ (el & 7)))];
#pragma unroll
            for (int c = 0; c < 4; c++) {
                int d = q * 4 + c;
                float wv0 = (c == 0) ? w0.x : (c == 1) ? w0.y : (c == 2) ? w0.z : w0.w;
                float wv1 = (c == 0) ? w1.x : (c == 1) ? w1.y : (c == 2) ? w1.z : w1.w;
                const ulonglong2* row = (const ulonglong2*)(sx + d * 16 + b0);
                ulonglong2 r0 = row[0];
                ulonglong2 r1 = row[1];
                u64 w20 = pack2(wv0, wv0);
                u64 w21 = pack2(wv1, wv1);
                fma2(acc[0][0], w20, r0.x);
                fma2(acc[0][1], w20, r0.y);
                fma2(acc[0][2], w20, r1.x);
                fma2(acc[0][3], w20, r1.y);
                fma2(acc[1][0], w21, r0.x);
                fma2(acc[1][1], w21, r0.y);
                fma2(acc[1][2], w21, r1.x);
                fma2(acc[1][3], w21, r1.y);
            }
        }

        int j = jb * 8 + jj;
#pragma unroll
        for (int i2 = 0; i2 < 2; i2++) {
            u64 b2 = pack2(bv[i2][jj], bv[i2][jj]);
            size_t base = (size_t)j * (IW * EE) + (size_t)(i0 + i2) * EE + e;
#pragma unroll
            for (int p = 0; p < 4; p++) {
                u64 uv = acc[i2][p];
                add2(uv, b2);
                add2(sacc[i2][p], uv);
                float lo, hi;
                unpack2(uv, lo, hi);
                g_u[base + (size_t)(b0 + 2 * p) * U_BSTRIDE]     = lo;
                g_u[base + (size_t)(b0 + 2 * p + 1) * U_BSTRIDE] = hi;
            }
        }

        if (jj < 7) {
            if (jj < 6) asm volatile("cp.async.wait_group 1;");
            else        asm volatile("cp.async.wait_group 0;");
            __syncthreads();
            if (jj < 5) issue(jj + 3);
        }
    }

#pragma unroll
    for (int i2 = 0; i2 < 2; i2++)
#pragma unroll
        for (int p = 0; p < 4; p++) {
            float lo, hi;
            unpack2(sacc[i2][p], lo, hi);
            atomicAdd(&g_S[0][(b0 + 2 * p) * (IW * EE) + (i0 + i2) * EE + e], lo);
            atomicAdd(&g_S[0][(b0 + 2 * p + 1) * (IW * EE) + (i0 + i2) * EE + e], hi);
        }
}

// ---------------- routing pass: 16 j/block, 512 thr, ring-3, 1 sync/j ------
// 16 warps; warp w owns capsule rows i = w and i = w+16.
template <int PASS>
__global__ void __launch_bounds__(512) k_route(int sin, int sout, float scale) {
    extern __shared__ __align__(16) float su[];   // [3][8192] = 96 KB
    __shared__ float a_s[2][IW];

    int jb = blockIdx.x;   // 0..15 (16 j per block)
    int b  = blockIdx.y;   // 0..15
    int tid = threadIdx.x, w = tid >> 5, l = tid & 31;

    const float* ubase = g_u + (size_t)b * U_BSTRIDE + (size_t)(jb * 16) * (IW * EE);

    auto issue = [&](int k) {
        const float4* src = (const float4*)(ubase + (size_t)k * (IW * EE));
        float4* dst = (float4*)(su + (k % 3) * 8192);
#pragma unroll
        for (int q = 0; q < 4; q++) {
            unsigned sp = (unsigned)__cvta_generic_to_shared(dst + tid + q * 512);
            asm volatile("cp.async.cg.shared.global [%0], [%1], 16;"
                         :: "r"(sp), "l"(src + tid + q * 512));
        }
        asm volatile("cp.async.commit_group;");
    };

    issue(0);
    issue(1);
    issue(2);

    // v in registers: warp w squashes rows i = w + 16s, s in {0,1}
    float4 va[2][2];
#pragma unroll
    for (int s = 0; s < 2; s++) {
        int i = w + s * 16;
        const float4* vp =
            (const float4*)(g_S[sin] + (size_t)b * IW * EE + i * EE + l * 8);
        float4 v0 = vp[0], v1 = vp[1];
        v0.x *= scale; v0.y *= scale; v0.z *= scale; v0.w *= scale;
        v1.x *= scale; v1.y *= scale; v1.z *= scale; v1.w *= scale;
        float ps = v0.x * v0.x + v0.y * v0.y + v0.z * v0.z + v0.w * v0.w +
                   v1.x * v1.x + v1.y * v1.y + v1.z * v1.z + v1.w * v1.w;
#pragma unroll
        for (int o = 16; o; o >>= 1) ps += __shfl_xor_sync(0xffffffffu, ps, o);
        float f = sqrtf(ps) / (1.0f + ps);
        v0.x *= f; v0.y *= f; v0.z *= f; v0.w *= f;
        v1.x *= f; v1.y *= f; v1.z *= f; v1.w *= f;
        va[s][0] = v0; va[s][1] = v1;
    }

    float4 sacc[2][2];
#pragma unroll
    for (int s = 0; s < 2; s++) {
        sacc[s][0] = make_float4(0.f, 0.f, 0.f, 0.f);
        sacc[s][1] = make_float4(0.f, 0.f, 0.f, 0.f);
    }

    asm volatile("cp.async.wait_group 2;");
    __syncthreads();   // stage 0 visible

    for (int k = 0; k < 16; k++) {
        int j = jb * 16 + k;

        const float* st = su + (k % 3) * 8192;
        float4 ur[2][2];
#pragma unroll
        for (int s = 0; s < 2; s++) {
            int i = w + s * 16;
            const float4* up = (const float4*)(st + i * 256 + l * 8);
            ur[s][0] = up[0];
            ur[s][1] = up[1];
            float dot = ur[s][0].x * va[s][0].x + ur[s][0].y * va[s][0].y +
                        ur[s][0].z * va[s][0].z + ur[s][0].w * va[s][0].w +
                        ur[s][1].x * va[s][1].x + ur[s][1].y * va[s][1].y +
                        ur[s][1].z * va[s][1].z + ur[s][1].w * va[s][1].w;
#pragma unroll
            for (int o = 16; o; o >>= 1) dot += __shfl_xor_sync(0xffffffffu, dot, o);
            if (l == 0) a_s[k & 1][i] = dot;
        }

        if (k < 14)       asm volatile("cp.async.wait_group 1;");
        else if (k == 14) asm volatile("cp.async.wait_group 0;");
        __syncthreads();   // a_s[k] ready; stage k+1 visible; stage k reusable

        if (k < 13) issue(k + 3);

        float z = a_s[k & 1][l];
        if (PASS == 2) {
            z += g_blog[((size_t)b * JJ + j) * IW + l];
        } else {
            if (w == 0) g_blog[((size_t)b * JJ + j) * IW + l] = z;
        }
        float mx = z;
#pragma unroll
        for (int o = 16; o; o >>= 1) mx = fmaxf(mx, __shfl_xor_sync(0xffffffffu, mx, o));
        float p = __expf(z - mx);
        float sm = p;
#pragma unroll
        for (int o = 16; o; o >>= 1) sm += __shfl_xor_sync(0xffffffffu, sm, o);
        float c_all = p / sm;

#pragma unroll
        for (int s = 0; s < 2; s++) {
            float c = __shfl_sync(0xffffffffu, c_all, w + s * 16);
            sacc[s][0].x = fmaf(c, ur[s][0].x, sacc[s][0].x);
            sacc[s][0].y = fmaf(c, ur[s][0].y, sacc[s][0].y);
            sacc[s][0].z = fmaf(c, ur[s][0].z, sacc[s][0].z);
            sacc[s][0].w = fmaf(c, ur[s][0].w, sacc[s][0].w);
            sacc[s][1].x = fmaf(c, ur[s][1].x, sacc[s][1].x);
            sacc[s][1].y = fmaf(c, ur[s][1].y, sacc[s][1].y);
            sacc[s][1].z = fmaf(c, ur[s][1].z, sacc[s][1].z);
            sacc[s][1].w = fmaf(c, ur[s][1].w, sacc[s][1].w);
        }
    }

    float* So = g_S[sout] + (size_t)b * IW * EE;
#pragma unroll
    for (int s = 0; s < 2; s++) {
        int i = w + s * 16;
        float* sp = &So[i * EE + l * 8];
        atomicAdd(sp + 0, sacc[s][0].x);
        atomicAdd(sp + 1, sacc[s][0].y);
        atomicAdd(sp + 2, sacc[s][0].z);
        atomicAdd(sp + 3, sacc[s][0].w);
        atomicAdd(sp + 4, sacc[s][1].x);
        atomicAdd(sp + 5, sacc[s][1].y);
        atomicAdd(sp + 6, sacc[s][1].z);
        atomicAdd(sp + 7, sacc[s][1].w);
    }
}

// ---------------- K8: output projection (fused final squash) ----------------
__global__ void __launch_bounds__(256) k_proj_out(const float* __restrict__ Wo,
                                                  const float* __restrict__ bo,
                                                  float* __restrict__ out) {
    int b  = blockIdx.y;
    int db = blockIdx.x;
    __shared__ float vvs[32][EE];
    __shared__ float wos[32][33];

    int tid = threadIdx.x;
    const float4* sg4 = (const float4*)(g_S[2] + (size_t)b * IW * EE);
    float4* vv4 = (float4*)vvs;
    for (int idx = tid; idx < IW * EE / 4; idx += 256) vv4[idx] = sg4[idx];
    __syncthreads();
    {
        int i = tid >> 3, seg = tid & 7;
        float ps = 0.f;
#pragma unroll
        for (int k = 0; k < 32; k++) {
            int e = seg * 32 + ((k + tid) & 31);
            float xv = vvs[i][e];
            ps = fmaf(xv, xv, ps);
        }
        ps += __shfl_xor_sync(0xffffffffu, ps, 1);
        ps += __shfl_xor_sync(0xffffffffu, ps, 2);
        ps += __shfl_xor_sync(0xffffffffu, ps, 4);
        float f = sqrtf(ps) / (1.0f + ps);
#pragma unroll
        for (int k = 0; k < 32; k++) {
            int e = seg * 32 + ((k + tid) & 31);
            vvs[i][e] *= f;
        }
    }

    int dl = tid & 31;
    int n0 = (tid >> 5) * 4;
    float acc[4] = {0.f, 0.f, 0.f, 0.f};

    for (int et = 0; et < 8; et++) {
        __syncthreads();
        {
            int r = tid >> 5, c = tid & 31;
            for (int rr = r; rr < 32; rr += 8)
                wos[rr][c] = Wo[(size_t)(db * 32 + rr) * EE + et * 32 + c];
        }
        __syncthreads();
#pragma unroll
        for (int k = 0; k < 32; k++) {
            float wv = wos[dl][k];
#pragma unroll
            for (int r = 0; r < 4; r++)
                acc[r] = fmaf(vvs[n0 + r][et * 32 + k], wv, acc[r]);
        }
    }

    int dm = db * 32 + dl;
    float bv = bo[dm];
#pragma unroll
    for (int r = 0; r < 4; r++)
        out[((size_t)b * WORDS + n0 + r) * DIM + dm] = acc[r] + bv;
}

// ---------------- launch ----------------
extern "C" void kernel_launch(void* const* d_in, const int* in_sizes, int n_in,
                              void* d_out, int out_size) {
    const float* x    = (const float*)d_in[0];
    const float* W    = (const float*)d_in[1];
    const float* bias = (const float*)d_in[2];
    const float* Wi   = (const float*)d_in[3];
    const float* bi   = (const float*)d_in[4];
    const float* Wo   = (const float*)d_in[5];
    const float* bo   = (const float*)d_in[6];
    float* out = (float*)d_out;

    static bool attr_done = false;
    if (!attr_done) {
        cudaFuncSetAttribute(k_proj_in,
                             cudaFuncAttributeMaxDynamicSharedMemorySize, 66688);
        cudaFuncSetAttribute(k_uhat,
                             cudaFuncAttributeMaxDynamicSharedMemorySize, 114688);
        cudaFuncSetAttribute(k_route<1>,
                             cudaFuncAttributeMaxDynamicSharedMemorySize, 98304);
        cudaFuncSetAttribute(k_route<2>,
                             cudaFuncAttributeMaxDynamicSharedMemorySize, 98304);
        attr_done = true;
    }

    k_zeroA<<<64, 256>>>();                                       // 1 (S0+S1)
    k_proj_in<<<dim3(8, BB), 256, 66688>>>(x, Wi, bi);            // 2
    k_uhat<<<dim3(32, 16, 2), 256, 114688>>>(W, bias);            // 3
    k_route<1><<<dim3(16, BB), 512, 98304>>>(0, 1, 1.0f / 32.0f); // 4 (ncu)
    k_zeroB<<<32, 256>>>();                                       // 5 (S2)
    k_route<2><<<dim3(16, BB), 512, 98304>>>(1, 2, 1.0f);         // 6
    k_proj_out<<<dim3(8, BB), 256>>>(Wo, bo, out);                // 7
}

// round 13
// speedup vs baseline: 1.1047x; 1.1047x over previous
#include <cuda_runtime.h>

// Problem dims
#define BB 16
#define WORDS 32
#define DIM 256
#define HEADS 8
#define DH 32
#define INNER 256
#define JJ 256     // WORDS*HEADS
#define IW 32      // output capsules (WORDS)
#define EE 256     // INNER

#define U_BSTRIDE ((size_t)JJ * IW * EE)

// ---------------- scratch (device globals; no allocations) ----------------
__device__ float g_xh[BB * JJ * DH];                  // [b][j][d]
__device__ float g_u[(size_t)BB * JJ * IW * EE];      // [b][j][i][e]  (128 MiB)
__device__ float g_S[3][BB * IW * EE];                // s accumulators per iter
__device__ float g_blog[BB * JJ * IW];                // routing logits

// ---------------- f32x2 helpers ----------------
typedef unsigned long long u64;

__device__ __forceinline__ u64 pack2(float lo, float hi) {
    u64 r;
    asm("mov.b64 %0, {%1, %2};" : "=l"(r)
        : "r"(__float_as_uint(lo)), "r"(__float_as_uint(hi)));
    return r;
}
__device__ __forceinline__ void unpack2(u64 v, float& lo, float& hi) {
    unsigned a, b;
    asm("mov.b64 {%0, %1}, %2;" : "=r"(a), "=r"(b) : "l"(v));
    lo = __uint_as_float(a);
    hi = __uint_as_float(b);
}
__device__ __forceinline__ void fma2(u64& acc, u64 a, u64 b) {
    asm("fma.rn.f32x2 %0, %1, %2, %0;" : "+l"(acc) : "l"(a), "l"(b));
}
__device__ __forceinline__ void add2(u64& acc, u64 a) {
    asm("add.rn.f32x2 %0, %1, %2;" : "=l"(acc) : "l"(acc), "l"(a));
}

// ---------------- K1: inner projection (fuses S0 zero) ----------------
__global__ void __launch_bounds__(256) k_proj_in(const float* __restrict__ x,
                                                 const float* __restrict__ Wi,
                                                 const float* __restrict__ bi) {
    extern __shared__ float dynpi[];
    float* xs = dynpi;              // [32][256]  32 KB
    float* ws = dynpi + 8192;       // [32][257]

    int eb = blockIdx.x;   // 0..7
    int b  = blockIdx.y;   // 0..15
    int tid = threadIdx.x;

    // zero my S0 slice: 2 MB / 128 blocks = 1024 float4
    {
        float4* z = (float4*)(&g_S[0][0]) + (size_t)(eb * 16 + b) * 1024;
#pragma unroll
        for (int r = 0; r < 4; r++)
            z[tid + r * 256] = make_float4(0.f, 0.f, 0.f, 0.f);
    }

    {
        const float4* xg = (const float4*)(x + (size_t)b * 32 * DIM);
        float4* xs4 = (float4*)xs;
#pragma unroll
        for (int r = 0; r < 8; r++) xs4[tid + r * 256] = xg[tid + r * 256];

        int rr = tid >> 5, c = tid & 31;
        for (int row = rr; row < 32; row += 8) {
            const float* wr = Wi + (size_t)(eb * 32 + row) * DIM;
#pragma unroll
            for (int kk = 0; kk < 8; kk++)
                ws[row * 257 + kk * 32 + c] = wr[kk * 32 + c];
        }
    }
    __syncthreads();

    int el = tid & 31;
    int n0 = (tid >> 5) * 4;
    float acc[4] = {0.f, 0.f, 0.f, 0.f};

#pragma unroll 4
    for (int k = 0; k < 256; k++) {
        float wv = ws[el * 257 + k];
#pragma unroll
        for (int r = 0; r < 4; r++)
            acc[r] = fmaf(xs[(n0 + r) * 256 + k], wv, acc[r]);
    }

    int ee = eb * 32 + el;
    float bv = bi[ee];
    int h = ee >> 5, d = ee & 31;
#pragma unroll
    for (int r = 0; r < 4; r++) {
        int n = n0 + r;
        g_xh[((size_t)b * JJ + n * HEADS + h) * DH + d] = acc[r] + bv;
    }
}

// ---------------- K2: u_hat einsum, persistent 4-unit blocks, single wave --
// Block blk handles units u0..u0+3, unit = (jb, ib, eh); all share jb.
// 32 stages (unit-local jj), ring-3 of 32 KB, 1 sync/stage. Fuses S1 zero.
__global__ void __launch_bounds__(256, 2) k_uhat(const float* __restrict__ W,
                                                 const float* __restrict__ bias) {
    extern __shared__ __align__(16) float dyn[];
    float4* ring = (float4*)dyn;             // [3][2048 float4] = 96 KB
    float*  sxh  = dyn + 3 * 8192;           // [8][32][16] = 16 KB

    int blk = blockIdx.x;  // 0..255
    int tid = threadIdx.x; // 0..255
    int el  = tid & 127;
    int bh  = tid >> 7;    // 0..1
    int b0  = bh * 8;
    int u0  = blk * 4;
    int jb  = u0 >> 5;     // same for all 4 units of this block

    // zero my S1 slice: 2 MB / 256 blocks = 512 float4
    {
        float4* z = (float4*)(&g_S[1][0]) + (size_t)blk * 512;
        z[tid]       = make_float4(0.f, 0.f, 0.f, 0.f);
        z[tid + 256] = make_float4(0.f, 0.f, 0.f, 0.f);
    }

    // fill sxh once (shared by all 4 units)
    for (int idx = tid; idx < 4096; idx += 256) {
        int jj  = idx >> 9;
        int rem = idx & 511;
        int b   = rem >> 5;
        int d   = rem & 31;
        sxh[jj * 512 + d * 16 + b] =
            g_xh[((size_t)b * JJ + jb * 8 + jj) * DH + d];
    }

    // stage s (0..31): unit = u0 + s/8, jj = s%8
    auto issue = [&](int s) {
        int un  = u0 + (s >> 3);
        int jj  = s & 7;
        int ib  = (un & 31) >> 1;
        int ehh = un & 1;
        int ii0 = ib * 2;
        int j   = jb * 8 + jj;
        float4* dst = ring + (s % 3) * 2048;
        const float4* s0p = (const float4*)W +
            (((size_t)j * IW + ii0) * EE + (size_t)ehh * 128) * 8;
        const float4* s1p = (const float4*)W +
            (((size_t)j * IW + ii0 + 1) * EE + (size_t)ehh * 128) * 8;
#pragma unroll
        for (int k = 0; k < 8; k++) {
            int idx = tid + k * 256;           // 0..2047
            int ih  = idx >> 10;               // 0..1
            int wi  = idx & 1023;
            int er  = wi >> 3, q = wi & 7;
            unsigned sp = (unsigned)__cvta_generic_to_shared(
                &dst[ih * 1024 + ((er << 3) | (q ^ (er & 7)))]);
            const float4* src = (ih == 0) ? (s0p + wi) : (s1p + wi);
            asm volatile("cp.async.cg.shared.global [%0], [%1], 16;"
                         :: "r"(sp), "l"(src));
        }
        asm volatile("cp.async.commit_group;");
    };

    issue(0);
    issue(1);
    issue(2);

    u64 sacc[2][4];
#pragma unroll
    for (int i2 = 0; i2 < 2; i2++)
#pragma unroll
        for (int p = 0; p < 4; p++) sacc[i2][p] = 0ull;

    asm volatile("cp.async.wait_group 2;");
    __syncthreads();   // stage 0 visible; sxh ready

    for (int s = 0; s < 32; s++) {
        int un  = u0 + (s >> 3);
        int jj  = s & 7;
        int ib  = (un & 31) >> 1;
        int ehh = un & 1;
        int ii0 = ib * 2;
        int e   = ehh * 128 + el;
        int j   = jb * 8 + jj;

        // bias loads (LDG latency hidden under the FMA block below)
        float bv0 = bias[((size_t)j * IW + ii0) * EE + e];
        float bv1 = bias[((size_t)j * IW + ii0 + 1) * EE + e];

        const float4* sw = ring + (s % 3) * 2048;
        const float*  sx = sxh + jj * 512;

        u64 acc[2][4];
#pragma unroll
        for (int i2 = 0; i2 < 2; i2++)
#pragma unroll
            for (int p = 0; p < 4; p++) acc[i2][p] = 0ull;

#pragma unroll
        for (int q = 0; q < 8; q++) {
            float4 w0 = sw[(el << 3) | (q ^ (el & 7))];
            float4 w1 = sw[1024 + ((el << 3) | (q ^ (el & 7)))];
#pragma unroll
            for (int c = 0; c < 4; c++) {
                int d = q * 4 + c;
                float wv0 = (c == 0) ? w0.x : (c == 1) ? w0.y : (c == 2) ? w0.z : w0.w;
                float wv1 = (c == 0) ? w1.x : (c == 1) ? w1.y : (c == 2) ? w1.z : w1.w;
                const ulonglong2* row = (const ulonglong2*)(sx + d * 16 + b0);
                ulonglong2 r0 = row[0];
                ulonglong2 r1 = row[1];
                u64 w20 = pack2(wv0, wv0);
                u64 w21 = pack2(wv1, wv1);
                fma2(acc[0][0], w20, r0.x);
                fma2(acc[0][1], w20, r0.y);
                fma2(acc[0][2], w20, r1.x);
                fma2(acc[0][3], w20, r1.y);
                fma2(acc[1][0], w21, r0.x);
                fma2(acc[1][1], w21, r0.y);
                fma2(acc[1][2], w21, r1.x);
                fma2(acc[1][3], w21, r1.y);
            }
        }

#pragma unroll
        for (int i2 = 0; i2 < 2; i2++) {
            u64 b2 = pack2(i2 ? bv1 : bv0, i2 ? bv1 : bv0);
            size_t base = (size_t)j * (IW * EE) + (size_t)(ii0 + i2) * EE + e;
#pragma unroll
            for (int p = 0; p < 4; p++) {
                u64 uv = acc[i2][p];
                add2(uv, b2);
                add2(sacc[i2][p], uv);
                float lo, hi;
                unpack2(uv, lo, hi);
                g_u[base + (size_t)(b0 + 2 * p) * U_BSTRIDE]     = lo;
                g_u[base + (size_t)(b0 + 2 * p + 1) * U_BSTRIDE] = hi;
            }
        }

        // unit boundary: flush iter-0 accumulation for this unit's (i0, e, b)
        if (jj == 7) {
#pragma unroll
            for (int i2 = 0; i2 < 2; i2++)
#pragma unroll
                for (int p = 0; p < 4; p++) {
                    float lo, hi;
                    unpack2(sacc[i2][p], lo, hi);
                    atomicAdd(&g_S[0][(b0 + 2 * p) * (IW * EE) +
                                      (ii0 + i2) * EE + e], lo);
                    atomicAdd(&g_S[0][(b0 + 2 * p + 1) * (IW * EE) +
                                      (ii0 + i2) * EE + e], hi);
                    sacc[i2][p] = 0ull;
                }
        }

        // 1-sync stage advance
        if (s < 31) {
            if (s < 30) asm volatile("cp.async.wait_group 1;");
            else        asm volatile("cp.async.wait_group 0;");
            __syncthreads();
            if (s < 29) issue(s + 3);
        }
    }
}

// ---------------- routing pass: 16 j/block, 512 thr, ring-3, 1 sync/j ------
// 16 warps; warp w owns capsule rows i = w and i = w+16. PASS1 zeroes S2.
template <int PASS>
__global__ void __launch_bounds__(512) k_route(int sin, int sout, float scale) {
    extern __shared__ __align__(16) float su[];   // [3][8192] = 96 KB
    __shared__ float a_s[2][IW];

    int jb = blockIdx.x;   // 0..15 (16 j per block)
    int b  = blockIdx.y;   // 0..15
    int tid = threadIdx.x, w = tid >> 5, l = tid & 31;

    const float* ubase = g_u + (size_t)b * U_BSTRIDE + (size_t)(jb * 16) * (IW * EE);

    auto issue = [&](int k) {
        const float4* src = (const float4*)(ubase + (size_t)k * (IW * EE));
        float4* dst = (float4*)(su + (k % 3) * 8192);
#pragma unroll
        for (int q = 0; q < 4; q++) {
            unsigned sp = (unsigned)__cvta_generic_to_shared(dst + tid + q * 512);
            asm volatile("cp.async.cg.shared.global [%0], [%1], 16;"
                         :: "r"(sp), "l"(src + tid + q * 512));
        }
        asm volatile("cp.async.commit_group;");
    };

    issue(0);
    issue(1);
    issue(2);

    if (PASS == 1) {   // zero my S2 slice: 2 MB / 256 blocks = 512 float4
        float4* z = (float4*)(&g_S[2][0]) + (size_t)(b * 16 + jb) * 512;
        z[tid] = make_float4(0.f, 0.f, 0.f, 0.f);
    }

    // v in registers: warp w squashes rows i = w + 16s, s in {0,1}
    float4 va[2][2];
#pragma unroll
    for (int s = 0; s < 2; s++) {
        int i = w + s * 16;
        const float4* vp =
            (const float4*)(g_S[sin] + (size_t)b * IW * EE + i * EE + l * 8);
        float4 v0 = vp[0], v1 = vp[1];
        v0.x *= scale; v0.y *= scale; v0.z *= scale; v0.w *= scale;
        v1.x *= scale; v1.y *= scale; v1.z *= scale; v1.w *= scale;
        float ps = v0.x * v0.x + v0.y * v0.y + v0.z * v0.z + v0.w * v0.w +
                   v1.x * v1.x + v1.y * v1.y + v1.z * v1.z + v1.w * v1.w;
#pragma unroll
        for (int o = 16; o; o >>= 1) ps += __shfl_xor_sync(0xffffffffu, ps, o);
        float f = sqrtf(ps) / (1.0f + ps);
        v0.x *= f; v0.y *= f; v0.z *= f; v0.w *= f;
        v1.x *= f; v1.y *= f; v1.z *= f; v1.w *= f;
        va[s][0] = v0; va[s][1] = v1;
    }

    float4 sacc[2][2];
#pragma unroll
    for (int s = 0; s < 2; s++) {
        sacc[s][0] = make_float4(0.f, 0.f, 0.f, 0.f);
        sacc[s][1] = make_float4(0.f, 0.f, 0.f, 0.f);
    }

    asm volatile("cp.async.wait_group 2;");
    __syncthreads();   // stage 0 visible

    for (int k = 0; k < 16; k++) {
        int j = jb * 16 + k;

        const float* st = su + (k % 3) * 8192;
        float4 ur[2][2];
#pragma unroll
        for (int s = 0; s < 2; s++) {
            int i = w + s * 16;
            const float4* up = (const float4*)(st + i * 256 + l * 8);
            ur[s][0] = up[0];
            ur[s][1] = up[1];
            float dot = ur[s][0].x * va[s][0].x + ur[s][0].y * va[s][0].y +
                        ur[s][0].z * va[s][0].z + ur[s][0].w * va[s][0].w +
                        ur[s][1].x * va[s][1].x + ur[s][1].y * va[s][1].y +
                        ur[s][1].z * va[s][1].z + ur[s][1].w * va[s][1].w;
#pragma unroll
            for (int o = 16; o; o >>= 1) dot += __shfl_xor_sync(0xffffffffu, dot, o);
            if (l == 0) a_s[k & 1][i] = dot;
        }

        if (k < 14)       asm volatile("cp.async.wait_group 1;");
        else if (k == 14) asm volatile("cp.async.wait_group 0;");
        __syncthreads();   // a_s[k] ready; stage k+1 visible; stage k reusable

        if (k < 13) issue(k + 3);

        float z = a_s[k & 1][l];
        if (PASS == 2) {
            z += g_blog[((size_t)b * JJ + j) * IW + l];
        } else {
            if (w == 0) g_blog[((size_t)b * JJ + j) * IW + l] = z;
        }
        float mx = z;
#pragma unroll
        for (int o = 16; o; o >>= 1) mx = fmaxf(mx, __shfl_xor_sync(0xffffffffu, mx, o));
        float p = __expf(z - mx);
        float sm = p;
#pragma unroll
        for (int o = 16; o; o >>= 1) sm += __shfl_xor_sync(0xffffffffu, sm, o);
        float c_all = p / sm;

#pragma unroll
        for (int s = 0; s < 2; s++) {
            float c = __shfl_sync(0xffffffffu, c_all, w + s * 16);
            sacc[s][0].x = fmaf(c, ur[s][0].x, sacc[s][0].x);
            sacc[s][0].y = fmaf(c, ur[s][0].y, sacc[s][0].y);
            sacc[s][0].z = fmaf(c, ur[s][0].z, sacc[s][0].z);
            sacc[s][0].w = fmaf(c, ur[s][0].w, sacc[s][0].w);
            sacc[s][1].x = fmaf(c, ur[s][1].x, sacc[s][1].x);
            sacc[s][1].y = fmaf(c, ur[s][1].y, sacc[s][1].y);
            sacc[s][1].z = fmaf(c, ur[s][1].z, sacc[s][1].z);
            sacc[s][1].w = fmaf(c, ur[s][1].w, sacc[s][1].w);
        }
    }

    float* So = g_S[sout] + (size_t)b * IW * EE;
#pragma unroll
    for (int s = 0; s < 2; s++) {
        int i = w + s * 16;
        float* sp = &So[i * EE + l * 8];
        atomicAdd(sp + 0, sacc[s][0].x);
        atomicAdd(sp + 1, sacc[s][0].y);
        atomicAdd(sp + 2, sacc[s][0].z);
        atomicAdd(sp + 3, sacc[s][0].w);
        atomicAdd(sp + 4, sacc[s][1].x);
        atomicAdd(sp + 5, sacc[s][1].y);
        atomicAdd(sp + 6, sacc[s][1].z);
        atomicAdd(sp + 7, sacc[s][1].w);
    }
}

// ---------------- K8: output projection (fused final squash) ----------------
__global__ void __launch_bounds__(256) k_proj_out(const float* __restrict__ Wo,
                                                  const float* __restrict__ bo,
                                                  float* __restrict__ out) {
    int b  = blockIdx.y;
    int db = blockIdx.x;
    __shared__ float vvs[32][EE];
    __shared__ float wos[32][33];

    int tid = threadIdx.x;
    const float4* sg4 = (const float4*)(g_S[2] + (size_t)b * IW * EE);
    float4* vv4 = (float4*)vvs;
    for (int idx = tid; idx < IW * EE / 4; idx += 256) vv4[idx] = sg4[idx];
    __syncthreads();
    {
        int i = tid >> 3, seg = tid & 7;
        float ps = 0.f;
#pragma unroll
        for (int k = 0; k < 32; k++) {
            int e = seg * 32 + ((k + tid) & 31);
            float xv = vvs[i][e];
            ps = fmaf(xv, xv, ps);
        }
        ps += __shfl_xor_sync(0xffffffffu, ps, 1);
        ps += __shfl_xor_sync(0xffffffffu, ps, 2);
        ps += __shfl_xor_sync(0xffffffffu, ps, 4);
        float f = sqrtf(ps) / (1.0f + ps);
#pragma unroll
        for (int k = 0; k < 32; k++) {
            int e = seg * 32 + ((k + tid) & 31);
            vvs[i][e] *= f;
        }
    }

    int dl = tid & 31;
    int n0 = (tid >> 5) * 4;
    float acc[4] = {0.f, 0.f, 0.f, 0.f};

    for (int et = 0; et < 8; et++) {
        __syncthreads();
        {
            int r = tid >> 5, c = tid & 31;
            for (int rr = r; rr < 32; rr += 8)
                wos[rr][c] = Wo[(size_t)(db * 32 + rr) * EE + et * 32 + c];
        }
        __syncthreads();
#pragma unroll
        for (int k = 0; k < 32; k++) {
            float wv = wos[dl][k];
#pragma unroll
            for (int r = 0; r < 4; r++)
                acc[r] = fmaf(vvs[n0 + r][et * 32 + k], wv, acc[r]);
        }
    }

    int dm = db * 32 + dl;
    float bv = bo[dm];
#pragma unroll
    for (int r = 0; r < 4; r++)
        out[((size_t)b * WORDS + n0 + r) * DIM + dm] = acc[r] + bv;
}

// ---------------- launch ----------------
extern "C" void kernel_launch(void* const* d_in, const int* in_sizes, int n_in,
                              void* d_out, int out_size) {
    const float* x    = (const float*)d_in[0];
    const float* W    = (const float*)d_in[1];
    const float* bias = (const float*)d_in[2];
    const float* Wi   = (const float*)d_in[3];
    const float* bi   = (const float*)d_in[4];
    const float* Wo   = (const float*)d_in[5];
    const float* bo   = (const float*)d_in[6];
    float* out = (float*)d_out;

    static bool attr_done = false;
    if (!attr_done) {
        cudaFuncSetAttribute(k_proj_in,
                             cudaFuncAttributeMaxDynamicSharedMemorySize, 66688);
        cudaFuncSetAttribute(k_uhat,
                             cudaFuncAttributeMaxDynamicSharedMemorySize, 114688);
        cudaFuncSetAttribute(k_route<1>,
                             cudaFuncAttributeMaxDynamicSharedMemorySize, 98304);
        cudaFuncSetAttribute(k_route<2>,
                             cudaFuncAttributeMaxDynamicSharedMemorySize, 98304);
        attr_done = true;
    }

    k_proj_in<<<dim3(8, BB), 256, 66688>>>(x, Wi, bi);            // 1 (zeros S0)
    k_uhat<<<256, 256, 114688>>>(W, bias);                        // 2 (zeros S1)
    k_route<1><<<dim3(16, BB), 512, 98304>>>(0, 1, 1.0f / 32.0f); // 3 (zeros S2)
    k_route<2><<<dim3(16, BB), 512, 98304>>>(1, 2, 1.0f);         // 4 (ncu)
    k_proj_out<<<dim3(8, BB), 256>>>(Wo, bo, out);                // 5
}